// round 15
// baseline (speedup 1.0000x reference)
#include <cuda_runtime.h>
#include <cuda_bf16.h>
#include <math.h>

#define N_NODES 16000
#define N_EDGES 256000

#define R_CUT 2.5f
#define SQ3     1.7320508075688772f
#define INV_SQ3 0.5773502691896258f
#define PI_F    3.14159265358979323846f

#define INV_SQRT32 0.17677669529663687f
#define W2_SCALE   0.051031036307982884f  // (1/sqrt16)*(1/sqrt24)
#define INV_SQRT16 0.25f
#define INV_SQRT8  0.3535533905932738f
#define INV_FAN    0.11180339887498948f   // 1/sqrt(80)
#define RAD_COEF   5.059644256269407f     // sqrt(2/2.5)*sqrt(32)

// ---- scratch ----
__device__ float    g_attn[N_EDGES];
__device__ float    g_Z[N_NODES];
__device__ float    g_qsw[N_NODES * 8];
__device__ float    g_qvw[N_NODES * 12];
// per edge: 16 words = bf16x2 of h: words 0-7 hi (t=0..15), 8-15 lo
__device__ unsigned g_hk[N_EDGES * 16];
__device__ unsigned g_hv[N_EDGES * 16];
__device__ float4   g_geo[N_EDGES];       // y10,y11,y12, valid-flag

// ---- packed fp32x2 helpers (basis kernel) ----
typedef unsigned long long u64t;
__device__ __forceinline__ u64t pkdup(float a) {
    u64t r; asm("mov.b64 %0, {%1, %1};" : "=l"(r) : "f"(a)); return r;
}
__device__ __forceinline__ float2 up2(u64t v) {
    float2 r; asm("mov.b64 {%0, %1}, %2;" : "=f"(r.x), "=f"(r.y) : "l"(v)); return r;
}
__device__ __forceinline__ void fma2(u64t& d, u64t a, u64t b) {
    asm("fma.rn.f32x2 %0, %1, %2, %3;" : "=l"(d) : "l"(a), "l"(b), "l"(d));
}
__device__ __forceinline__ float silu_fast(float a) {
    return __fdividef(a, 1.f + __expf(-a));
}

// 2-way bf16 split
__device__ __forceinline__ void bsplit(float a, unsigned short& hi, unsigned short& lo) {
    hi = __bfloat16_as_ushort(__float2bfloat16(a));
    float r1 = a - __bfloat162float(__ushort_as_bfloat16(hi));
    lo = __bfloat16_as_ushort(__float2bfloat16(r1));
}
__device__ __forceinline__ void bsplit2x2(float a, float b, unsigned& whi, unsigned& wlo) {
    unsigned short ah, al, bh, bl;
    bsplit(a, ah, al);
    bsplit(b, bh, bl);
    whi = ((unsigned)bh << 16) | (unsigned)ah;
    wlo = ((unsigned)bl << 16) | (unsigned)al;
}

// mma.sync m16n8k16 bf16 (row.col), f32 accum
__device__ __forceinline__ void mma16816(float* d,
                                         unsigned a0, unsigned a1, unsigned a2, unsigned a3,
                                         unsigned b0, unsigned b1) {
    asm volatile(
        "mma.sync.aligned.m16n8k16.row.col.f32.bf16.bf16.f32 "
        "{%0,%1,%2,%3}, {%4,%5,%6,%7}, {%8,%9}, {%0,%1,%2,%3};"
        : "+f"(d[0]), "+f"(d[1]), "+f"(d[2]), "+f"(d[3])
        : "r"(a0), "r"(a1), "r"(a2), "r"(a3), "r"(b0), "r"(b1));
}

// =====================================================================
// Kernel 1: per-node q (pre-contracted with Ws)
// =====================================================================
__global__ void node_prep_kernel(const float* __restrict__ x,
                                 const float* __restrict__ Wq_s,
                                 const float* __restrict__ Wq_v,
                                 const float* __restrict__ Ws_ss,
                                 const float* __restrict__ Ws_vv)
{
    int n = blockIdx.x * blockDim.x + threadIdx.x;
    if (n >= N_NODES) return;
    const float* xr = x + n * 40;

    float xs[16], xv[24];
    #pragma unroll
    for (int i = 0; i < 16; i++) xs[i] = xr[i];
    #pragma unroll
    for (int i = 0; i < 24; i++) xv[i] = xr[16 + i];

    float qs[8];
    #pragma unroll
    for (int o = 0; o < 8; o++) {
        float a = 0.f;
        #pragma unroll
        for (int i = 0; i < 16; i++) a = fmaf(xs[i], __ldg(&Wq_s[i * 8 + o]), a);
        qs[o] = a * INV_SQRT16;
    }
    float qv[12];
    #pragma unroll
    for (int o = 0; o < 4; o++)
        #pragma unroll
        for (int c = 0; c < 3; c++) {
            float a = 0.f;
            #pragma unroll
            for (int i = 0; i < 8; i++) a = fmaf(xv[i * 3 + c], __ldg(&Wq_v[i * 4 + o]), a);
            qv[o * 3 + c] = a * INV_SQRT8;
        }

    #pragma unroll
    for (int p = 0; p < 8; p++) {
        float a = 0.f;
        #pragma unroll
        for (int o = 0; o < 8; o++) a = fmaf(qs[o], __ldg(&Ws_ss[o * 8 + p]), a);
        g_qsw[n * 8 + p] = a * INV_FAN;
    }
    const float invfs = INV_FAN / SQ3;
    #pragma unroll
    for (int p = 0; p < 4; p++)
        #pragma unroll
        for (int c = 0; c < 3; c++) {
            float a = 0.f;
            #pragma unroll
            for (int o = 0; o < 4; o++) a = fmaf(qv[o * 3 + c], __ldg(&Ws_vv[o * 4 + p]), a);
            g_qvw[n * 12 + p * 3 + c] = a * invfs;
        }
}

// =====================================================================
// Kernel 2: basis — geometry + both MLP hidden layers (2-way bf16 split)
// =====================================================================
__global__ void __launch_bounds__(256)
basis_kernel(const float* __restrict__ pos,
             const float* __restrict__ Wk1, const float* __restrict__ Wv1,
             const int* __restrict__ esrc, const int* __restrict__ edst)
{
    __shared__ float sW[1024];   // Wk1 (512) | Wv1 (512), pre-scaled
    const int tid = threadIdx.x;
    for (int i = tid; i < 512; i += 256) sW[i] = Wk1[i] * INV_SQRT32;
    for (int i = tid; i < 512; i += 256) sW[512 + i] = Wv1[i] * INV_SQRT32;
    __syncthreads();
    const ulonglong2* wkq = (const ulonglong2*)sW;           // [n*4+q]
    const ulonglong2* wvq = (const ulonglong2*)(sW + 512);

    const int e = blockIdx.x * 256 + tid;
    const int ns = esrc[e];
    const int nd = edst[e];

    float vx = pos[nd * 3 + 0] - pos[ns * 3 + 0];
    float vy = pos[nd * 3 + 1] - pos[ns * 3 + 1];
    float vz = pos[nd * 3 + 2] - pos[ns * 3 + 2];
    float d = sqrtf(vx * vx + vy * vy + vz * vz);
    const int valid = (d < R_CUT);
    const float dsafe = fmaxf(d, 1e-6f);
    const float invd = 1.0f / dsafe;
    float y10 = 0.f, y11 = 0.f, y12 = 0.f, coef = 0.f;
    if (valid) {
        y10 = SQ3 * vx * invd; y11 = SQ3 * vy * invd; y12 = SQ3 * vz * invd;
        coef = RAD_COEF * invd;
    }
    const float theta = (PI_F / R_CUT) * dsafe;

    u64t akp[8], avp[8];
    #pragma unroll
    for (int t2 = 0; t2 < 8; t2++) { akp[t2] = 0ull; avp[t2] = 0ull; }
    float sth, cth;
    sincosf(theta, &sth, &cth);
    const float twoc = 2.0f * cth;
    float s_nm1 = 0.f, s_n = sth;
    #pragma unroll 1
    for (int n = 0; n < 32; n++) {
        u64t r2 = pkdup(coef * s_n);
        const ulonglong2* wk = wkq + n * 4;
        const ulonglong2* wv = wvq + n * 4;
        #pragma unroll
        for (int q = 0; q < 4; q++) {
            ulonglong2 a = wk[q];
            fma2(akp[2 * q], r2, a.x);
            fma2(akp[2 * q + 1], r2, a.y);
            ulonglong2 b = wv[q];
            fma2(avp[2 * q], r2, b.x);
            fma2(avp[2 * q + 1], r2, b.y);
        }
        float s_nx = fmaf(twoc, s_n, -s_nm1);
        s_nm1 = s_n; s_n = s_nx;
    }

    unsigned* hkw = g_hk + e * 16;
    unsigned* hvw = g_hv + e * 16;
    #pragma unroll
    for (int t2 = 0; t2 < 8; t2++) {
        float2 a = up2(akp[t2]);
        unsigned hi, lo;
        bsplit2x2(silu_fast(a.x), silu_fast(a.y), hi, lo);
        hkw[t2] = hi; hkw[8 + t2] = lo;
        float2 b = up2(avp[t2]);
        bsplit2x2(silu_fast(b.x), silu_fast(b.y), hi, lo);
        hvw[t2] = hi; hvw[8 + t2] = lo;
    }
    g_geo[e] = make_float4(y10, y11, y12, valid ? 1.f : 0.f);
}

// =====================================================================
// GEMM via mma.sync, split precision D = Ahi*Bhi + Ahi*Blo + Alo*Bhi.
// 32-column chunks, immediate per-tile store (low regs), small sD.
// B row layout permuted so each fragment pair is one LDS.64:
//   new word 2u   = orig word u      (u<4)   -> (b0, _)
//   new word 2u+1 = orig word u+4             -> (_, b1)
// =====================================================================
#define APITCH 20
#define BPITCH 20
#define DPITCH 34
#define SA_U32   (128 * APITCH)                  // 2560
#define SMD_K    (SA_U32 + 288 * BPITCH)         // 8320
#define SM_TOT_K ((SMD_K + 128 * DPITCH) * 4)    // 50688
#define SMD_V    (SA_U32 + 576 * BPITCH)         // 14080
#define SM_TOT_V ((SMD_V + 128 * DPITCH) * 4)    // 73728

#define GEMM_PROLOG(W2, LD, NROWS, SMD, HSRC)                                        \
    extern __shared__ char smem[];                                                   \
    unsigned* sA32 = (unsigned*)smem;                                                \
    unsigned* sB32 = ((unsigned*)smem) + SA_U32;                                     \
    unsigned short* sB16 = (unsigned short*)sB32;                                    \
    float* sD = ((float*)smem) + (SMD);                                              \
    const int tid = threadIdx.x;                                                     \
    const int e = blockIdx.x * 128 + tid;                                            \
    const int lane = tid & 31;                                                       \
    const int g = lane >> 2, cc = lane & 3;                                          \
    const int wbase = (tid >> 5) * 32;                                               \
    /* stage B hi/lo with pair-permuted word layout */                               \
    for (int idx = tid; idx < 16 * (NROWS); idx += 128) {                            \
        int t = idx / (NROWS), n = idx - t * (NROWS);                                \
        float v = __ldg(&(W2)[t * (LD) + n]) * W2_SCALE;                             \
        unsigned short bh, bl;                                                       \
        bsplit(v, bh, bl);                                                           \
        int u = t >> 1, hh = t & 1;                                                  \
        int nw = (u < 4) ? (2 * u) : (2 * (u - 4) + 1);                              \
        sB16[n * (2 * BPITCH) + nw * 2 + hh] = bh;                                   \
        sB16[n * (2 * BPITCH) + 16 + nw * 2 + hh] = bl;                              \
    }                                                                                \
    /* stage A: this thread's edge row (16 words: hi 0-7, lo 8-15), pitch 20 */      \
    {                                                                                \
        const uint4* hp = (const uint4*)((HSRC) + e * 16);                           \
        unsigned* ar = sA32 + tid * APITCH;                                          \
        _Pragma("unroll")                                                            \
        for (int q4 = 0; q4 < 4; q4++) {                                             \
            uint4 hq = hp[q4];                                                       \
            ar[q4 * 4 + 0] = hq.x; ar[q4 * 4 + 1] = hq.y;                            \
            ar[q4 * 4 + 2] = hq.z; ar[q4 * 4 + 3] = hq.w;                            \
        }                                                                            \
    }                                                                                \
    __syncthreads();                                                                 \
    /* A fragments: [mt][limb s: 0=hi,1=lo][4] */                                    \
    unsigned afr[2][2][4];                                                           \
    _Pragma("unroll")                                                                \
    for (int mt = 0; mt < 2; mt++)                                                   \
        _Pragma("unroll")                                                            \
        for (int s = 0; s < 2; s++) {                                                \
            int r0 = wbase + mt * 16 + g;                                            \
            afr[mt][s][0] = sA32[r0 * APITCH + 8 * s + cc];                          \
            afr[mt][s][1] = sA32[(r0 + 8) * APITCH + 8 * s + cc];                    \
            afr[mt][s][2] = sA32[r0 * APITCH + 8 * s + 4 + cc];                      \
            afr[mt][s][3] = sA32[(r0 + 8) * APITCH + 8 * s + 4 + cc];                \
        }

// 32 columns per chunk: 4 n-tiles, immediate store per (q, mt)
#define GEMM_CHUNK(chunk)                                                            \
    {                                                                                \
        _Pragma("unroll")                                                            \
        for (int q = 0; q < 4; q++) {                                                \
            int nrow = (chunk) * 32 + q * 8 + g;                                     \
            uint2 bh2 = *(const uint2*)&sB32[nrow * BPITCH + 2 * cc];                \
            uint2 bl2 = *(const uint2*)&sB32[nrow * BPITCH + 8 + 2 * cc];            \
            _Pragma("unroll")                                                        \
            for (int mt = 0; mt < 2; mt++) {                                         \
                float dacc[4] = {0.f, 0.f, 0.f, 0.f};                                \
                mma16816(dacc, afr[mt][0][0], afr[mt][0][1], afr[mt][0][2],          \
                         afr[mt][0][3], bh2.x, bh2.y);  /* hi*hi */                  \
                mma16816(dacc, afr[mt][0][0], afr[mt][0][1], afr[mt][0][2],          \
                         afr[mt][0][3], bl2.x, bl2.y);  /* hi*lo */                  \
                mma16816(dacc, afr[mt][1][0], afr[mt][1][1], afr[mt][1][2],          \
                         afr[mt][1][3], bh2.x, bh2.y);  /* lo*hi */                  \
                int r0 = wbase + mt * 16 + g;                                        \
                int cl = q * 8 + 2 * cc;                                             \
                *(float2*)&sD[r0 * DPITCH + cl] = make_float2(dacc[0], dacc[1]);     \
                *(float2*)&sD[(r0 + 8) * DPITCH + cl] = make_float2(dacc[2], dacc[3]); \
            }                                                                        \
        }                                                                            \
        __syncthreads();                                                             \
    }

__device__ __forceinline__ void load_features(const float* __restrict__ x, int ns,
                                              float* xs, float* xv) {
    const float4* xr4 = (const float4*)(x + ns * 40);
    float4 a = xr4[0], b = xr4[1], c = xr4[2], dd = xr4[3];
    xs[0]=a.x; xs[1]=a.y; xs[2]=a.z; xs[3]=a.w;
    xs[4]=b.x; xs[5]=b.y; xs[6]=b.z; xs[7]=b.w;
    xs[8]=c.x; xs[9]=c.y; xs[10]=c.z; xs[11]=c.w;
    xs[12]=dd.x; xs[13]=dd.y; xs[14]=dd.z; xs[15]=dd.w;
    float4 e = xr4[4], f = xr4[5], g2 = xr4[6], h = xr4[7], i2 = xr4[8], j = xr4[9];
    xv[0]=e.x; xv[1]=e.y; xv[2]=e.z; xv[3]=e.w;
    xv[4]=f.x; xv[5]=f.y; xv[6]=f.z; xv[7]=f.w;
    xv[8]=g2.x; xv[9]=g2.y; xv[10]=g2.z; xv[11]=g2.w;
    xv[12]=h.x; xv[13]=h.y; xv[14]=h.z; xv[15]=h.w;
    xv[16]=i2.x; xv[17]=i2.y; xv[18]=i2.z; xv[19]=i2.w;
    xv[20]=j.x; xv[21]=j.y; xv[22]=j.z; xv[23]=j.w;
}

// ---- K kernel: 288 cols of Wk2 (9 chunks) -> attn, Z ----
__global__ void __launch_bounds__(128, 3)
gemm_k_kernel(const float* __restrict__ x, const float* __restrict__ Wk2,
              const int* __restrict__ esrc, const int* __restrict__ edst)
{
    GEMM_PROLOG(Wk2, 288, 288, SMD_K, g_hk)

    const int ns = esrc[e];
    const int nd = edst[e];
    float xs[16], xv[24];
    load_features(x, ns, xs, xv);
    float4 geo = g_geo[e];
    const float y10 = geo.x, y11 = geo.y, y12 = geo.z;
    float uv[8];
    #pragma unroll
    for (int i = 0; i < 8; i++)
        uv[i] = (xv[i*3+0]*y10 + xv[i*3+1]*y11 + xv[i*3+2]*y12) * INV_SQ3;

    float ks[8] = {0,0,0,0,0,0,0,0};
    float kv0[4] = {0,0,0,0}, kv1[4] = {0,0,0,0}, kv2[4] = {0,0,0,0};

    #pragma unroll
    for (int chunk = 0; chunk < 9; chunk++) {
        GEMM_CHUNK(chunk)
        #pragma unroll
        for (int jl2 = 0; jl2 < 16; jl2++) {
            float2 w2 = *(const float2*)&sD[tid * DPITCH + jl2 * 2];
            #pragma unroll
            for (int h2 = 0; h2 < 2; h2++) {
                const int j = chunk * 32 + jl2 * 2 + h2;
                float w = (h2 == 0) ? w2.x : w2.y;
                if (j < 128) {
                    ks[j & 7] = fmaf(xs[j >> 3], w, ks[j & 7]);
                } else if (j < 192) {
                    ks[j & 7] = fmaf(uv[(j - 128) >> 3], w, ks[j & 7]);
                } else if (j < 256) {
                    const int o = (j - 192) & 3;
                    float t = xs[(j - 192) >> 2] * w;
                    kv0[o] = fmaf(t, y10, kv0[o]);
                    kv1[o] = fmaf(t, y11, kv1[o]);
                    kv2[o] = fmaf(t, y12, kv2[o]);
                } else {
                    const int o = (j - 256) & 3, i = (j - 256) >> 2;
                    kv0[o] = fmaf(xv[i*3+0], w, kv0[o]);
                    kv1[o] = fmaf(xv[i*3+1], w, kv1[o]);
                    kv2[o] = fmaf(xv[i*3+2], w, kv2[o]);
                }
            }
        }
        __syncthreads();
    }

    const float* qsw = g_qsw + nd * 8;
    const float* qvw = g_qvw + nd * 12;
    float sim = 0.f;
    #pragma unroll
    for (int o = 0; o < 8; o++) sim = fmaf(qsw[o], ks[o], sim);
    #pragma unroll
    for (int o = 0; o < 4; o++) {
        sim = fmaf(qvw[o*3+0], kv0[o], sim);
        sim = fmaf(qvw[o*3+1], kv1[o], sim);
        sim = fmaf(qvw[o*3+2], kv2[o], sim);
    }
    float attn = expf(sim);
    g_attn[e] = attn;
    atomicAdd(&g_Z[nd], attn);
}

// ---- V kernel: all 576 cols of Wv2 (18 chunks) -> scatter a*v ----
__global__ void __launch_bounds__(128, 3)
gemm_v_kernel(const float* __restrict__ x, const float* __restrict__ Wv2,
              const int* __restrict__ esrc, const int* __restrict__ edst,
              float* __restrict__ out)
{
    GEMM_PROLOG(Wv2, 576, 576, SMD_V, g_hv)

    const int ns = esrc[e];
    const int nd = edst[e];
    float xs[16], xv[24];
    load_features(x, ns, xs, xv);
    float4 geo = g_geo[e];
    const float y10 = geo.x, y11 = geo.y, y12 = geo.z;
    float uv[8];
    #pragma unroll
    for (int i = 0; i < 8; i++)
        uv[i] = (xv[i*3+0]*y10 + xv[i*3+1]*y11 + xv[i*3+2]*y12) * INV_SQ3;
    const float a_norm = g_attn[e] / g_Z[nd];

    float vs[16];
    float vv0[8], vv1[8], vv2[8];
    #pragma unroll
    for (int o = 0; o < 16; o++) vs[o] = 0.f;
    #pragma unroll
    for (int o = 0; o < 8; o++) { vv0[o] = 0.f; vv1[o] = 0.f; vv2[o] = 0.f; }

    #pragma unroll
    for (int chunk = 0; chunk < 18; chunk++) {
        GEMM_CHUNK(chunk)
        #pragma unroll
        for (int jl2 = 0; jl2 < 16; jl2++) {
            float2 w2 = *(const float2*)&sD[tid * DPITCH + jl2 * 2];
            #pragma unroll
            for (int h2 = 0; h2 < 2; h2++) {
                const int j = chunk * 32 + jl2 * 2 + h2;
                float w = (h2 == 0) ? w2.x : w2.y;
                if (j < 256) {
                    vs[j & 15] = fmaf(xs[j >> 4], w, vs[j & 15]);
                } else if (j < 384) {
                    vs[j & 15] = fmaf(uv[(j - 256) >> 4], w, vs[j & 15]);
                } else if (j < 512) {
                    const int o = (j - 384) & 7;
                    float t = xs[(j - 384) >> 3] * w;
                    vv0[o] = fmaf(t, y10, vv0[o]);
                    vv1[o] = fmaf(t, y11, vv1[o]);
                    vv2[o] = fmaf(t, y12, vv2[o]);
                } else {
                    const int o = (j - 512) & 7, i = (j - 512) >> 3;
                    vv0[o] = fmaf(xv[i*3+0], w, vv0[o]);
                    vv1[o] = fmaf(xv[i*3+1], w, vv1[o]);
                    vv2[o] = fmaf(xv[i*3+2], w, vv2[o]);
                }
            }
        }
        __syncthreads();
    }

    if (geo.w != 0.f) {
        float* orow = out + nd * 40;
        #pragma unroll
        for (int o = 0; o < 16; o++) atomicAdd(&orow[o], a_norm * vs[o]);
        #pragma unroll
        for (int o = 0; o < 8; o++) {
            atomicAdd(&orow[16 + o*3 + 0], a_norm * vv0[o]);
            atomicAdd(&orow[16 + o*3 + 1], a_norm * vv1[o]);
            atomicAdd(&orow[16 + o*3 + 2], a_norm * vv2[o]);
        }
    }
}

// =====================================================================
extern "C" void kernel_launch(void* const* d_in, const int* in_sizes, int n_in,
                              void* d_out, int out_size)
{
    const float* pos   = (const float*)d_in[0];
    const float* x     = (const float*)d_in[1];
    const float* Wq_s  = (const float*)d_in[2];
    const float* Wq_v  = (const float*)d_in[3];
    const float* Wk1   = (const float*)d_in[4];
    const float* Wk2   = (const float*)d_in[5];
    const float* Wv1   = (const float*)d_in[6];
    const float* Wv2   = (const float*)d_in[7];
    const float* Ws_ss = (const float*)d_in[8];
    const float* Ws_vv = (const float*)d_in[9];
    const int*   esrc  = (const int*)d_in[10];
    const int*   edst  = (const int*)d_in[11];
    float* out = (float*)d_out;
    (void)in_sizes; (void)n_in; (void)out_size;

    cudaFuncSetAttribute(gemm_k_kernel, cudaFuncAttributeMaxDynamicSharedMemorySize, SM_TOT_K);
    cudaFuncSetAttribute(gemm_v_kernel, cudaFuncAttributeMaxDynamicSharedMemorySize, SM_TOT_V);

    void* zptr = nullptr;
    cudaGetSymbolAddress(&zptr, g_Z);
    cudaMemsetAsync(zptr, 0, N_NODES * sizeof(float), 0);
    cudaMemsetAsync(out, 0, N_NODES * 40 * sizeof(float), 0);

    node_prep_kernel<<<(N_NODES + 255) / 256, 256>>>(x, Wq_s, Wq_v, Ws_ss, Ws_vv);
    basis_kernel<<<N_EDGES / 256, 256>>>(pos, Wk1, Wv1, esrc, edst);
    gemm_k_kernel<<<N_EDGES / 128, 128, SM_TOT_K>>>(x, Wk2, esrc, edst);
    gemm_v_kernel<<<N_EDGES / 128, 128, SM_TOT_V>>>(x, Wv2, esrc, edst, out);
}

// round 16
// speedup vs baseline: 1.2146x; 1.2146x over previous
#include <cuda_runtime.h>
#include <cuda_bf16.h>
#include <math.h>

#define N_NODES 16000
#define N_EDGES 256000

#define R_CUT 2.5f
#define SQ3     1.7320508075688772f
#define INV_SQ3 0.5773502691896258f
#define PI_F    3.14159265358979323846f

#define INV_SQRT32 0.17677669529663687f
#define W2_SCALE   0.051031036307982884f  // (1/sqrt16)*(1/sqrt24)
#define INV_SQRT16 0.25f
#define INV_SQRT8  0.3535533905932738f
#define INV_FAN    0.11180339887498948f   // 1/sqrt(80)
#define RAD_COEF   5.059644256269407f     // sqrt(2/2.5)*sqrt(32)

// ---- scratch ----
__device__ float    g_attn[N_EDGES];
__device__ float    g_Z[N_NODES];
__device__ float    g_qsw[N_NODES * 8];
__device__ float    g_qvw[N_NODES * 12];
// per edge: 16 words = bf16x2 of h: words 0-7 hi (t=0..15), 8-15 lo
__device__ unsigned g_hk[N_EDGES * 16];
__device__ unsigned g_hv[N_EDGES * 16];
__device__ float4   g_geo[N_EDGES];       // y10,y11,y12, valid-flag

// ---- packed fp32x2 helpers (basis kernel) ----
typedef unsigned long long u64t;
__device__ __forceinline__ u64t pkdup(float a) {
    u64t r; asm("mov.b64 %0, {%1, %1};" : "=l"(r) : "f"(a)); return r;
}
__device__ __forceinline__ float2 up2(u64t v) {
    float2 r; asm("mov.b64 {%0, %1}, %2;" : "=f"(r.x), "=f"(r.y) : "l"(v)); return r;
}
__device__ __forceinline__ void fma2(u64t& d, u64t a, u64t b) {
    asm("fma.rn.f32x2 %0, %1, %2, %3;" : "=l"(d) : "l"(a), "l"(b), "l"(d));
}
__device__ __forceinline__ float silu_fast(float a) {
    return __fdividef(a, 1.f + __expf(-a));
}

// 2-way bf16 split
__device__ __forceinline__ void bsplit(float a, unsigned short& hi, unsigned short& lo) {
    hi = __bfloat16_as_ushort(__float2bfloat16(a));
    float r1 = a - __bfloat162float(__ushort_as_bfloat16(hi));
    lo = __bfloat16_as_ushort(__float2bfloat16(r1));
}
__device__ __forceinline__ void bsplit2x2(float a, float b, unsigned& whi, unsigned& wlo) {
    unsigned short ah, al, bh, bl;
    bsplit(a, ah, al);
    bsplit(b, bh, bl);
    whi = ((unsigned)bh << 16) | (unsigned)ah;
    wlo = ((unsigned)bl << 16) | (unsigned)al;
}

// mma.sync m16n8k16 bf16 (row.col), f32 accum
__device__ __forceinline__ void mma16816(float* d,
                                         unsigned a0, unsigned a1, unsigned a2, unsigned a3,
                                         unsigned b0, unsigned b1) {
    asm volatile(
        "mma.sync.aligned.m16n8k16.row.col.f32.bf16.bf16.f32 "
        "{%0,%1,%2,%3}, {%4,%5,%6,%7}, {%8,%9}, {%0,%1,%2,%3};"
        : "+f"(d[0]), "+f"(d[1]), "+f"(d[2]), "+f"(d[3])
        : "r"(a0), "r"(a1), "r"(a2), "r"(a3), "r"(b0), "r"(b1));
}

// =====================================================================
// Kernel 1: per-node q (pre-contracted with Ws)
// =====================================================================
__global__ void node_prep_kernel(const float* __restrict__ x,
                                 const float* __restrict__ Wq_s,
                                 const float* __restrict__ Wq_v,
                                 const float* __restrict__ Ws_ss,
                                 const float* __restrict__ Ws_vv)
{
    int n = blockIdx.x * blockDim.x + threadIdx.x;
    if (n >= N_NODES) return;
    const float* xr = x + n * 40;

    float xs[16], xv[24];
    #pragma unroll
    for (int i = 0; i < 16; i++) xs[i] = xr[i];
    #pragma unroll
    for (int i = 0; i < 24; i++) xv[i] = xr[16 + i];

    float qs[8];
    #pragma unroll
    for (int o = 0; o < 8; o++) {
        float a = 0.f;
        #pragma unroll
        for (int i = 0; i < 16; i++) a = fmaf(xs[i], __ldg(&Wq_s[i * 8 + o]), a);
        qs[o] = a * INV_SQRT16;
    }
    float qv[12];
    #pragma unroll
    for (int o = 0; o < 4; o++)
        #pragma unroll
        for (int c = 0; c < 3; c++) {
            float a = 0.f;
            #pragma unroll
            for (int i = 0; i < 8; i++) a = fmaf(xv[i * 3 + c], __ldg(&Wq_v[i * 4 + o]), a);
            qv[o * 3 + c] = a * INV_SQRT8;
        }

    #pragma unroll
    for (int p = 0; p < 8; p++) {
        float a = 0.f;
        #pragma unroll
        for (int o = 0; o < 8; o++) a = fmaf(qs[o], __ldg(&Ws_ss[o * 8 + p]), a);
        g_qsw[n * 8 + p] = a * INV_FAN;
    }
    const float invfs = INV_FAN / SQ3;
    #pragma unroll
    for (int p = 0; p < 4; p++)
        #pragma unroll
        for (int c = 0; c < 3; c++) {
            float a = 0.f;
            #pragma unroll
            for (int o = 0; o < 4; o++) a = fmaf(qv[o * 3 + c], __ldg(&Ws_vv[o * 4 + p]), a);
            g_qvw[n * 12 + p * 3 + c] = a * invfs;
        }
}

// =====================================================================
// Kernel 2: basis — geometry + both MLP hidden layers (2-way bf16 split)
// =====================================================================
__global__ void __launch_bounds__(256)
basis_kernel(const float* __restrict__ pos,
             const float* __restrict__ Wk1, const float* __restrict__ Wv1,
             const int* __restrict__ esrc, const int* __restrict__ edst)
{
    __shared__ float sW[1024];   // Wk1 (512) | Wv1 (512), pre-scaled
    const int tid = threadIdx.x;
    for (int i = tid; i < 512; i += 256) sW[i] = Wk1[i] * INV_SQRT32;
    for (int i = tid; i < 512; i += 256) sW[512 + i] = Wv1[i] * INV_SQRT32;
    __syncthreads();
    const ulonglong2* wkq = (const ulonglong2*)sW;           // [n*4+q]
    const ulonglong2* wvq = (const ulonglong2*)(sW + 512);

    const int e = blockIdx.x * 256 + tid;
    const int ns = esrc[e];
    const int nd = edst[e];

    float vx = pos[nd * 3 + 0] - pos[ns * 3 + 0];
    float vy = pos[nd * 3 + 1] - pos[ns * 3 + 1];
    float vz = pos[nd * 3 + 2] - pos[ns * 3 + 2];
    float d = sqrtf(vx * vx + vy * vy + vz * vz);
    const int valid = (d < R_CUT);
    const float dsafe = fmaxf(d, 1e-6f);
    const float invd = 1.0f / dsafe;
    float y10 = 0.f, y11 = 0.f, y12 = 0.f, coef = 0.f;
    if (valid) {
        y10 = SQ3 * vx * invd; y11 = SQ3 * vy * invd; y12 = SQ3 * vz * invd;
        coef = RAD_COEF * invd;
    }
    const float theta = (PI_F / R_CUT) * dsafe;

    u64t akp[8], avp[8];
    #pragma unroll
    for (int t2 = 0; t2 < 8; t2++) { akp[t2] = 0ull; avp[t2] = 0ull; }
    float sth, cth;
    sincosf(theta, &sth, &cth);
    const float twoc = 2.0f * cth;
    float s_nm1 = 0.f, s_n = sth;
    #pragma unroll 1
    for (int n = 0; n < 32; n++) {
        u64t r2 = pkdup(coef * s_n);
        const ulonglong2* wk = wkq + n * 4;
        const ulonglong2* wv = wvq + n * 4;
        #pragma unroll
        for (int q = 0; q < 4; q++) {
            ulonglong2 a = wk[q];
            fma2(akp[2 * q], r2, a.x);
            fma2(akp[2 * q + 1], r2, a.y);
            ulonglong2 b = wv[q];
            fma2(avp[2 * q], r2, b.x);
            fma2(avp[2 * q + 1], r2, b.y);
        }
        float s_nx = fmaf(twoc, s_n, -s_nm1);
        s_nm1 = s_n; s_n = s_nx;
    }

    unsigned* hkw = g_hk + e * 16;
    unsigned* hvw = g_hv + e * 16;
    #pragma unroll
    for (int t2 = 0; t2 < 8; t2++) {
        float2 a = up2(akp[t2]);
        unsigned hi, lo;
        bsplit2x2(silu_fast(a.x), silu_fast(a.y), hi, lo);
        hkw[t2] = hi; hkw[8 + t2] = lo;
        float2 b = up2(avp[t2]);
        bsplit2x2(silu_fast(b.x), silu_fast(b.y), hi, lo);
        hvw[t2] = hi; hvw[8 + t2] = lo;
    }
    g_geo[e] = make_float4(y10, y11, y12, valid ? 1.f : 0.f);
}

// =====================================================================
// GEMM via mma.sync, split precision D = Ahi*Bhi + Ahi*Blo + Alo*Bhi.
// R14 layouts (conflict-free, pitch 20/20/73), 72-col chunks.
// NEW: per-chunk sync is __syncwarp (sD rows are warp-private);
//      B staged in 288-row halves (one 23KB buffer) -> 70.7KB smem, 3 CTAs.
// =====================================================================
#define APITCH 20
#define BPITCH 20
#define DPITCH 73
#define SA_U32   (128 * APITCH)                  // 2560
#define SB_U32   (288 * BPITCH)                  // 5760
#define SMD_F    (SA_U32 + SB_U32)               // 8320
#define SM_TOT   ((SMD_F + 128 * DPITCH) * 4)    // 70656

#define GEMM_PROLOG_A(HSRC)                                                          \
    extern __shared__ char smem[];                                                   \
    unsigned* sA32 = (unsigned*)smem;                                                \
    unsigned* sB32 = ((unsigned*)smem) + SA_U32;                                     \
    unsigned short* sB16 = (unsigned short*)sB32;                                    \
    float* sD = ((float*)smem) + SMD_F;                                              \
    const int tid = threadIdx.x;                                                     \
    const int e = blockIdx.x * 128 + tid;                                            \
    const int lane = tid & 31;                                                       \
    const int g = lane >> 2, cc = lane & 3;                                          \
    const int wbase = (tid >> 5) * 32;                                               \
    /* stage A: this thread's edge row (16 words: hi 0-7, lo 8-15), pitch 20 */      \
    {                                                                                \
        const uint4* hp = (const uint4*)((HSRC) + e * 16);                           \
        unsigned* ar = sA32 + tid * APITCH;                                          \
        _Pragma("unroll")                                                            \
        for (int q4 = 0; q4 < 4; q4++) {                                             \
            uint4 hq = hp[q4];                                                       \
            ar[q4 * 4 + 0] = hq.x; ar[q4 * 4 + 1] = hq.y;                            \
            ar[q4 * 4 + 2] = hq.z; ar[q4 * 4 + 3] = hq.w;                            \
        }                                                                            \
    }                                                                                \
    __syncthreads();                                                                 \
    /* A fragments: [mt][limb s: 0=hi,1=lo][4] */                                    \
    unsigned afr[2][2][4];                                                           \
    _Pragma("unroll")                                                                \
    for (int mt = 0; mt < 2; mt++)                                                   \
        _Pragma("unroll")                                                            \
        for (int s = 0; s < 2; s++) {                                                \
            int r0 = wbase + mt * 16 + g;                                            \
            afr[mt][s][0] = sA32[r0 * APITCH + 8 * s + cc];                          \
            afr[mt][s][1] = sA32[(r0 + 8) * APITCH + 8 * s + cc];                    \
            afr[mt][s][2] = sA32[r0 * APITCH + 8 * s + 4 + cc];                      \
            afr[mt][s][3] = sA32[(r0 + 8) * APITCH + 8 * s + 4 + cc];                \
        }

// stage 288 B rows (cols COLBASE..+287 of W2) into the shared buffer
#define STAGE_B(W2, LD, COLBASE)                                                     \
    for (int idx = tid; idx < 16 * 288; idx += 128) {                                \
        int t = idx / 288, n = idx - t * 288;                                        \
        float v = __ldg(&(W2)[t * (LD) + (COLBASE) + n]) * W2_SCALE;                 \
        unsigned short bh, bl;                                                       \
        bsplit(v, bh, bl);                                                           \
        sB16[n * (2 * BPITCH) + t] = bh;                                             \
        sB16[n * (2 * BPITCH) + 16 + t] = bl;                                        \
    }

// one 72-col chunk: mma + store (warp-private sD region), then warp sync
#define GEMM_CHUNK(chunk)                                                            \
    {                                                                                \
        _Pragma("unroll")                                                            \
        for (int nt = 0; nt < 9; nt++) {                                             \
            int nrow = (chunk) * 72 + nt * 8 + g;                                    \
            unsigned b0h = sB32[nrow * BPITCH + cc];                                 \
            unsigned b1h = sB32[nrow * BPITCH + 4 + cc];                             \
            unsigned b0l = sB32[nrow * BPITCH + 8 + cc];                             \
            unsigned b1l = sB32[nrow * BPITCH + 12 + cc];                            \
            _Pragma("unroll")                                                        \
            for (int mt = 0; mt < 2; mt++) {                                         \
                float dacc[4] = {0.f, 0.f, 0.f, 0.f};                                \
                mma16816(dacc, afr[mt][0][0], afr[mt][0][1], afr[mt][0][2],          \
                         afr[mt][0][3], b0h, b1h);  /* hi*hi */                      \
                mma16816(dacc, afr[mt][0][0], afr[mt][0][1], afr[mt][0][2],          \
                         afr[mt][0][3], b0l, b1l);  /* hi*lo */                      \
                mma16816(dacc, afr[mt][1][0], afr[mt][1][1], afr[mt][1][2],          \
                         afr[mt][1][3], b0h, b1h);  /* lo*hi */                      \
                int r0 = wbase + mt * 16 + g;                                        \
                int cl = nt * 8 + 2 * cc;                                            \
                sD[r0 * DPITCH + cl]       = dacc[0];                                \
                sD[r0 * DPITCH + cl + 1]   = dacc[1];                                \
                sD[(r0 + 8) * DPITCH + cl]     = dacc[2];                            \
                sD[(r0 + 8) * DPITCH + cl + 1] = dacc[3];                            \
            }                                                                        \
        }                                                                            \
        __syncwarp();                                                                \
    }

__device__ __forceinline__ void load_features(const float* __restrict__ x, int ns,
                                              float* xs, float* xv) {
    const float4* xr4 = (const float4*)(x + ns * 40);
    float4 a = xr4[0], b = xr4[1], c = xr4[2], dd = xr4[3];
    xs[0]=a.x; xs[1]=a.y; xs[2]=a.z; xs[3]=a.w;
    xs[4]=b.x; xs[5]=b.y; xs[6]=b.z; xs[7]=b.w;
    xs[8]=c.x; xs[9]=c.y; xs[10]=c.z; xs[11]=c.w;
    xs[12]=dd.x; xs[13]=dd.y; xs[14]=dd.z; xs[15]=dd.w;
    float4 e = xr4[4], f = xr4[5], g2 = xr4[6], h = xr4[7], i2 = xr4[8], j = xr4[9];
    xv[0]=e.x; xv[1]=e.y; xv[2]=e.z; xv[3]=e.w;
    xv[4]=f.x; xv[5]=f.y; xv[6]=f.z; xv[7]=f.w;
    xv[8]=g2.x; xv[9]=g2.y; xv[10]=g2.z; xv[11]=g2.w;
    xv[12]=h.x; xv[13]=h.y; xv[14]=h.z; xv[15]=h.w;
    xv[16]=i2.x; xv[17]=i2.y; xv[18]=i2.z; xv[19]=i2.w;
    xv[20]=j.x; xv[21]=j.y; xv[22]=j.z; xv[23]=j.w;
}

// ---- K kernel: 288 cols of Wk2 (1 half, 4 chunks) -> attn, Z ----
__global__ void __launch_bounds__(128, 3)
gemm_k_kernel(const float* __restrict__ x, const float* __restrict__ Wk2,
              const int* __restrict__ esrc, const int* __restrict__ edst)
{
    GEMM_PROLOG_A(g_hk)
    STAGE_B(Wk2, 288, 0)

    const int ns = esrc[e];
    const int nd = edst[e];
    float xs[16], xv[24];
    load_features(x, ns, xs, xv);
    float4 geo = g_geo[e];
    const float y10 = geo.x, y11 = geo.y, y12 = geo.z;
    float uv[8];
    #pragma unroll
    for (int i = 0; i < 8; i++)
        uv[i] = (xv[i*3+0]*y10 + xv[i*3+1]*y11 + xv[i*3+2]*y12) * INV_SQ3;
    __syncthreads();   // B staged

    float ks[8] = {0,0,0,0,0,0,0,0};
    float kv0[4] = {0,0,0,0}, kv1[4] = {0,0,0,0}, kv2[4] = {0,0,0,0};

    #pragma unroll
    for (int chunk = 0; chunk < 4; chunk++) {
        GEMM_CHUNK(chunk)
        #pragma unroll
        for (int jl = 0; jl < 72; jl++) {
            const int j = chunk * 72 + jl;
            float w = sD[tid * DPITCH + jl];
            if (j < 128) {
                ks[j & 7] = fmaf(xs[j >> 3], w, ks[j & 7]);
            } else if (j < 192) {
                ks[j & 7] = fmaf(uv[(j - 128) >> 3], w, ks[j & 7]);
            } else if (j < 256) {
                const int o = (j - 192) & 3;
                float t = xs[(j - 192) >> 2] * w;
                kv0[o] = fmaf(t, y10, kv0[o]);
                kv1[o] = fmaf(t, y11, kv1[o]);
                kv2[o] = fmaf(t, y12, kv2[o]);
            } else {
                const int o = (j - 256) & 3, i = (j - 256) >> 2;
                kv0[o] = fmaf(xv[i*3+0], w, kv0[o]);
                kv1[o] = fmaf(xv[i*3+1], w, kv1[o]);
                kv2[o] = fmaf(xv[i*3+2], w, kv2[o]);
            }
        }
        __syncwarp();
    }

    const float* qsw = g_qsw + nd * 8;
    const float* qvw = g_qvw + nd * 12;
    float sim = 0.f;
    #pragma unroll
    for (int o = 0; o < 8; o++) sim = fmaf(qsw[o], ks[o], sim);
    #pragma unroll
    for (int o = 0; o < 4; o++) {
        sim = fmaf(qvw[o*3+0], kv0[o], sim);
        sim = fmaf(qvw[o*3+1], kv1[o], sim);
        sim = fmaf(qvw[o*3+2], kv2[o], sim);
    }
    float attn = expf(sim);
    g_attn[e] = attn;
    atomicAdd(&g_Z[nd], attn);
}

// ---- V kernel: 576 cols of Wv2 (2 halves x 4 chunks) -> scatter a*v ----
__global__ void __launch_bounds__(128, 3)
gemm_v_kernel(const float* __restrict__ x, const float* __restrict__ Wv2,
              const int* __restrict__ esrc, const int* __restrict__ edst,
              float* __restrict__ out)
{
    GEMM_PROLOG_A(g_hv)

    const int ns = esrc[e];
    const int nd = edst[e];
    float xs[16], xv[24];
    load_features(x, ns, xs, xv);
    float4 geo = g_geo[e];
    const float y10 = geo.x, y11 = geo.y, y12 = geo.z;
    float uv[8];
    #pragma unroll
    for (int i = 0; i < 8; i++)
        uv[i] = (xv[i*3+0]*y10 + xv[i*3+1]*y11 + xv[i*3+2]*y12) * INV_SQ3;
    const float a_norm = g_attn[e] / g_Z[nd];

    float vs[16];
    float vv0[8], vv1[8], vv2[8];
    #pragma unroll
    for (int o = 0; o < 16; o++) vs[o] = 0.f;
    #pragma unroll
    for (int o = 0; o < 8; o++) { vv0[o] = 0.f; vv1[o] = 0.f; vv2[o] = 0.f; }

    #pragma unroll
    for (int half = 0; half < 2; half++) {
        __syncthreads();   // all warps done with previous B half
        STAGE_B(Wv2, 576, half * 288)
        __syncthreads();   // B half staged

        #pragma unroll
        for (int chunk = 0; chunk < 4; chunk++) {
            GEMM_CHUNK(chunk)
            #pragma unroll
            for (int jl = 0; jl < 72; jl++) {
                const int j = half * 288 + chunk * 72 + jl;
                float w = sD[tid * DPITCH + jl];
                if (j < 256) {
                    vs[j & 15] = fmaf(xs[j >> 4], w, vs[j & 15]);
                } else if (j < 384) {
                    vs[j & 15] = fmaf(uv[(j - 256) >> 4], w, vs[j & 15]);
                } else if (j < 512) {
                    const int o = (j - 384) & 7;
                    float t = xs[(j - 384) >> 3] * w;
                    vv0[o] = fmaf(t, y10, vv0[o]);
                    vv1[o] = fmaf(t, y11, vv1[o]);
                    vv2[o] = fmaf(t, y12, vv2[o]);
                } else {
                    const int o = (j - 512) & 7, i = (j - 512) >> 3;
                    vv0[o] = fmaf(xv[i*3+0], w, vv0[o]);
                    vv1[o] = fmaf(xv[i*3+1], w, vv1[o]);
                    vv2[o] = fmaf(xv[i*3+2], w, vv2[o]);
                }
            }
            __syncwarp();
        }
    }

    if (geo.w != 0.f) {
        float* orow = out + nd * 40;
        #pragma unroll
        for (int o = 0; o < 16; o++) atomicAdd(&orow[o], a_norm * vs[o]);
        #pragma unroll
        for (int o = 0; o < 8; o++) {
            atomicAdd(&orow[16 + o*3 + 0], a_norm * vv0[o]);
            atomicAdd(&orow[16 + o*3 + 1], a_norm * vv1[o]);
            atomicAdd(&orow[16 + o*3 + 2], a_norm * vv2[o]);
        }
    }
}

// =====================================================================
extern "C" void kernel_launch(void* const* d_in, const int* in_sizes, int n_in,
                              void* d_out, int out_size)
{
    const float* pos   = (const float*)d_in[0];
    const float* x     = (const float*)d_in[1];
    const float* Wq_s  = (const float*)d_in[2];
    const float* Wq_v  = (const float*)d_in[3];
    const float* Wk1   = (const float*)d_in[4];
    const float* Wk2   = (const float*)d_in[5];
    const float* Wv1   = (const float*)d_in[6];
    const float* Wv2   = (const float*)d_in[7];
    const float* Ws_ss = (const float*)d_in[8];
    const float* Ws_vv = (const float*)d_in[9];
    const int*   esrc  = (const int*)d_in[10];
    const int*   edst  = (const int*)d_in[11];
    float* out = (float*)d_out;
    (void)in_sizes; (void)n_in; (void)out_size;

    cudaFuncSetAttribute(gemm_k_kernel, cudaFuncAttributeMaxDynamicSharedMemorySize, SM_TOT);
    cudaFuncSetAttribute(gemm_v_kernel, cudaFuncAttributeMaxDynamicSharedMemorySize, SM_TOT);

    void* zptr = nullptr;
    cudaGetSymbolAddress(&zptr, g_Z);
    cudaMemsetAsync(zptr, 0, N_NODES * sizeof(float), 0);
    cudaMemsetAsync(out, 0, N_NODES * 40 * sizeof(float), 0);

    node_prep_kernel<<<(N_NODES + 255) / 256, 256>>>(x, Wq_s, Wq_v, Ws_ss, Ws_vv);
    basis_kernel<<<N_EDGES / 256, 256>>>(pos, Wk1, Wv1, esrc, edst);
    gemm_k_kernel<<<N_EDGES / 128, 128, SM_TOT>>>(x, Wk2, esrc, edst);
    gemm_v_kernel<<<N_EDGES / 128, 128, SM_TOT>>>(x, Wv2, esrc, edst, out);
}

// round 17
// speedup vs baseline: 1.2536x; 1.0321x over previous
#include <cuda_runtime.h>
#include <cuda_bf16.h>
#include <math.h>

#define N_NODES 16000
#define N_EDGES 256000

#define R_CUT 2.5f
#define SQ3     1.7320508075688772f
#define INV_SQ3 0.5773502691896258f
#define PI_F    3.14159265358979323846f

#define INV_SQRT32 0.17677669529663687f
#define W2_SCALE   0.051031036307982884f  // (1/sqrt16)*(1/sqrt24)
#define INV_SQRT16 0.25f
#define INV_SQRT8  0.3535533905932738f
#define INV_FAN    0.11180339887498948f   // 1/sqrt(80)
#define RAD_COEF   5.059644256269407f     // sqrt(2/2.5)*sqrt(32)

// ---- scratch ----
__device__ float    g_Z[N_NODES];
__device__ float    g_qsw[N_NODES * 8];
__device__ float    g_qvw[N_NODES * 12];
// per edge: 16 words = bf16x2 of h: words 0-7 hi (t=0..15), 8-15 lo
__device__ unsigned g_hk[N_EDGES * 16];
__device__ unsigned g_hv[N_EDGES * 16];
__device__ float4   g_geo[N_EDGES];       // y10,y11,y12, valid-flag

// ---- packed fp32x2 helpers (basis kernel) ----
typedef unsigned long long u64t;
__device__ __forceinline__ u64t pkdup(float a) {
    u64t r; asm("mov.b64 %0, {%1, %1};" : "=l"(r) : "f"(a)); return r;
}
__device__ __forceinline__ float2 up2(u64t v) {
    float2 r; asm("mov.b64 {%0, %1}, %2;" : "=f"(r.x), "=f"(r.y) : "l"(v)); return r;
}
__device__ __forceinline__ void fma2(u64t& d, u64t a, u64t b) {
    asm("fma.rn.f32x2 %0, %1, %2, %3;" : "=l"(d) : "l"(a), "l"(b), "l"(d));
}
__device__ __forceinline__ float silu_fast(float a) {
    return __fdividef(a, 1.f + __expf(-a));
}

// 2-way bf16 split
__device__ __forceinline__ void bsplit(float a, unsigned short& hi, unsigned short& lo) {
    hi = __bfloat16_as_ushort(__float2bfloat16(a));
    float r1 = a - __bfloat162float(__ushort_as_bfloat16(hi));
    lo = __bfloat16_as_ushort(__float2bfloat16(r1));
}
__device__ __forceinline__ void bsplit2x2(float a, float b, unsigned& whi, unsigned& wlo) {
    unsigned short ah, al, bh, bl;
    bsplit(a, ah, al);
    bsplit(b, bh, bl);
    whi = ((unsigned)bh << 16) | (unsigned)ah;
    wlo = ((unsigned)bl << 16) | (unsigned)al;
}

// mma.sync m16n8k16 bf16 (row.col), f32 accum
__device__ __forceinline__ void mma16816(float* d,
                                         unsigned a0, unsigned a1, unsigned a2, unsigned a3,
                                         unsigned b0, unsigned b1) {
    asm volatile(
        "mma.sync.aligned.m16n8k16.row.col.f32.bf16.bf16.f32 "
        "{%0,%1,%2,%3}, {%4,%5,%6,%7}, {%8,%9}, {%0,%1,%2,%3};"
        : "+f"(d[0]), "+f"(d[1]), "+f"(d[2]), "+f"(d[3])
        : "r"(a0), "r"(a1), "r"(a2), "r"(a3), "r"(b0), "r"(b1));
}

// =====================================================================
// Kernel 1: per-node q (pre-contracted with Ws)
// =====================================================================
__global__ void node_prep_kernel(const float* __restrict__ x,
                                 const float* __restrict__ Wq_s,
                                 const float* __restrict__ Wq_v,
                                 const float* __restrict__ Ws_ss,
                                 const float* __restrict__ Ws_vv)
{
    int n = blockIdx.x * blockDim.x + threadIdx.x;
    if (n >= N_NODES) return;
    const float* xr = x + n * 40;

    float xs[16], xv[24];
    #pragma unroll
    for (int i = 0; i < 16; i++) xs[i] = xr[i];
    #pragma unroll
    for (int i = 0; i < 24; i++) xv[i] = xr[16 + i];

    float qs[8];
    #pragma unroll
    for (int o = 0; o < 8; o++) {
        float a = 0.f;
        #pragma unroll
        for (int i = 0; i < 16; i++) a = fmaf(xs[i], __ldg(&Wq_s[i * 8 + o]), a);
        qs[o] = a * INV_SQRT16;
    }
    float qv[12];
    #pragma unroll
    for (int o = 0; o < 4; o++)
        #pragma unroll
        for (int c = 0; c < 3; c++) {
            float a = 0.f;
            #pragma unroll
            for (int i = 0; i < 8; i++) a = fmaf(xv[i * 3 + c], __ldg(&Wq_v[i * 4 + o]), a);
            qv[o * 3 + c] = a * INV_SQRT8;
        }

    #pragma unroll
    for (int p = 0; p < 8; p++) {
        float a = 0.f;
        #pragma unroll
        for (int o = 0; o < 8; o++) a = fmaf(qs[o], __ldg(&Ws_ss[o * 8 + p]), a);
        g_qsw[n * 8 + p] = a * INV_FAN;
    }
    const float invfs = INV_FAN / SQ3;
    #pragma unroll
    for (int p = 0; p < 4; p++)
        #pragma unroll
        for (int c = 0; c < 3; c++) {
            float a = 0.f;
            #pragma unroll
            for (int o = 0; o < 4; o++) a = fmaf(qv[o * 3 + c], __ldg(&Ws_vv[o * 4 + p]), a);
            g_qvw[n * 12 + p * 3 + c] = a * invfs;
        }
}

// =====================================================================
// Kernel 2: basis — geometry + both MLP hidden layers (2-way bf16 split)
// =====================================================================
__global__ void __launch_bounds__(256)
basis_kernel(const float* __restrict__ pos,
             const float* __restrict__ Wk1, const float* __restrict__ Wv1,
             const int* __restrict__ esrc, const int* __restrict__ edst)
{
    __shared__ float sW[1024];   // Wk1 (512) | Wv1 (512), pre-scaled
    const int tid = threadIdx.x;
    for (int i = tid; i < 512; i += 256) sW[i] = Wk1[i] * INV_SQRT32;
    for (int i = tid; i < 512; i += 256) sW[512 + i] = Wv1[i] * INV_SQRT32;
    __syncthreads();
    const ulonglong2* wkq = (const ulonglong2*)sW;           // [n*4+q]
    const ulonglong2* wvq = (const ulonglong2*)(sW + 512);

    const int e = blockIdx.x * 256 + tid;
    const int ns = esrc[e];
    const int nd = edst[e];

    float vx = pos[nd * 3 + 0] - pos[ns * 3 + 0];
    float vy = pos[nd * 3 + 1] - pos[ns * 3 + 1];
    float vz = pos[nd * 3 + 2] - pos[ns * 3 + 2];
    float d = sqrtf(vx * vx + vy * vy + vz * vz);
    const int valid = (d < R_CUT);
    const float dsafe = fmaxf(d, 1e-6f);
    const float invd = 1.0f / dsafe;
    float y10 = 0.f, y11 = 0.f, y12 = 0.f, coef = 0.f;
    if (valid) {
        y10 = SQ3 * vx * invd; y11 = SQ3 * vy * invd; y12 = SQ3 * vz * invd;
        coef = RAD_COEF * invd;
    }
    const float theta = (PI_F / R_CUT) * dsafe;

    u64t akp[8], avp[8];
    #pragma unroll
    for (int t2 = 0; t2 < 8; t2++) { akp[t2] = 0ull; avp[t2] = 0ull; }
    float sth, cth;
    sincosf(theta, &sth, &cth);
    const float twoc = 2.0f * cth;
    float s_nm1 = 0.f, s_n = sth;
    #pragma unroll 1
    for (int n = 0; n < 32; n++) {
        u64t r2 = pkdup(coef * s_n);
        const ulonglong2* wk = wkq + n * 4;
        const ulonglong2* wv = wvq + n * 4;
        #pragma unroll
        for (int q = 0; q < 4; q++) {
            ulonglong2 a = wk[q];
            fma2(akp[2 * q], r2, a.x);
            fma2(akp[2 * q + 1], r2, a.y);
            ulonglong2 b = wv[q];
            fma2(avp[2 * q], r2, b.x);
            fma2(avp[2 * q + 1], r2, b.y);
        }
        float s_nx = fmaf(twoc, s_n, -s_nm1);
        s_nm1 = s_n; s_n = s_nx;
    }

    unsigned* hkw = g_hk + e * 16;
    unsigned* hvw = g_hv + e * 16;
    #pragma unroll
    for (int t2 = 0; t2 < 8; t2++) {
        float2 a = up2(akp[t2]);
        unsigned hi, lo;
        bsplit2x2(silu_fast(a.x), silu_fast(a.y), hi, lo);
        hkw[t2] = hi; hkw[8 + t2] = lo;
        float2 b = up2(avp[t2]);
        bsplit2x2(silu_fast(b.x), silu_fast(b.y), hi, lo);
        hvw[t2] = hi; hvw[8 + t2] = lo;
    }
    g_geo[e] = make_float4(y10, y11, y12, valid ? 1.f : 0.f);
}

// =====================================================================
// Merged K+V GEMM kernel. Split precision D = Ahi*Bhi + Ahi*Blo + Alo*Bhi.
// Phase K: attn (register) + Z; Phase V: scatter raw attn*v.
// Normalization by Z deferred to a per-node epilogue kernel.
// =====================================================================
#define APITCH 20
#define BPITCH 20
#define DPITCH 74
#define SA_U32   (128 * APITCH)                  // 2560
#define SB_U32   (288 * BPITCH)                  // 5760
#define SMD_F    (SA_U32 + SB_U32)               // 8320
#define SM_TOT   ((SMD_F + 128 * DPITCH) * 4)    // 71168

#define STAGE_A(HSRC)                                                                \
    {                                                                                \
        const uint4* hp = (const uint4*)((HSRC) + e * 16);                           \
        unsigned* ar = sA32 + tid * APITCH;                                          \
        _Pragma("unroll")                                                            \
        for (int q4 = 0; q4 < 4; q4++) {                                             \
            uint4 hq = hp[q4];                                                       \
            ar[q4 * 4 + 0] = hq.x; ar[q4 * 4 + 1] = hq.y;                            \
            ar[q4 * 4 + 2] = hq.z; ar[q4 * 4 + 3] = hq.w;                            \
        }                                                                            \
    }

#define LOAD_AFR()                                                                   \
    _Pragma("unroll")                                                                \
    for (int mt = 0; mt < 2; mt++)                                                   \
        _Pragma("unroll")                                                            \
        for (int s = 0; s < 2; s++) {                                                \
            int r0 = wbase + mt * 16 + g;                                            \
            afr[mt][s][0] = sA32[r0 * APITCH + 8 * s + cc];                          \
            afr[mt][s][1] = sA32[(r0 + 8) * APITCH + 8 * s + cc];                    \
            afr[mt][s][2] = sA32[r0 * APITCH + 8 * s + 4 + cc];                      \
            afr[mt][s][3] = sA32[(r0 + 8) * APITCH + 8 * s + 4 + cc];                \
        }

// stage 288 B rows (cols COLBASE..+287 of W2)
#define STAGE_B(W2, LD, COLBASE)                                                     \
    for (int idx = tid; idx < 16 * 288; idx += 128) {                                \
        int t = idx / 288, n = idx - t * 288;                                        \
        float v = __ldg(&(W2)[t * (LD) + (COLBASE) + n]) * W2_SCALE;                 \
        unsigned short bh, bl;                                                       \
        bsplit(v, bh, bl);                                                           \
        sB16[n * (2 * BPITCH) + t] = bh;                                             \
        sB16[n * (2 * BPITCH) + 16 + t] = bl;                                        \
    }

// one 72-col chunk: mma + float2 store (warp-private sD region), warp sync
#define GEMM_CHUNK(chunk)                                                            \
    {                                                                                \
        _Pragma("unroll")                                                            \
        for (int nt = 0; nt < 9; nt++) {                                             \
            int nrow = (chunk) * 72 + nt * 8 + g;                                    \
            unsigned b0h = sB32[nrow * BPITCH + cc];                                 \
            unsigned b1h = sB32[nrow * BPITCH + 4 + cc];                             \
            unsigned b0l = sB32[nrow * BPITCH + 8 + cc];                             \
            unsigned b1l = sB32[nrow * BPITCH + 12 + cc];                            \
            _Pragma("unroll")                                                        \
            for (int mt = 0; mt < 2; mt++) {                                         \
                float dacc[4] = {0.f, 0.f, 0.f, 0.f};                                \
                mma16816(dacc, afr[mt][0][0], afr[mt][0][1], afr[mt][0][2],          \
                         afr[mt][0][3], b0h, b1h);  /* hi*hi */                      \
                mma16816(dacc, afr[mt][0][0], afr[mt][0][1], afr[mt][0][2],          \
                         afr[mt][0][3], b0l, b1l);  /* hi*lo */                      \
                mma16816(dacc, afr[mt][1][0], afr[mt][1][1], afr[mt][1][2],          \
                         afr[mt][1][3], b0h, b1h);  /* lo*hi */                      \
                int r0 = wbase + mt * 16 + g;                                        \
                int cl = nt * 8 + 2 * cc;                                            \
                *(float2*)&sD[r0 * DPITCH + cl] = make_float2(dacc[0], dacc[1]);     \
                *(float2*)&sD[(r0 + 8) * DPITCH + cl] = make_float2(dacc[2], dacc[3]); \
            }                                                                        \
        }                                                                            \
        __syncwarp();                                                                \
    }

__device__ __forceinline__ void load_features(const float* __restrict__ x, int ns,
                                              float* xs, float* xv) {
    const float4* xr4 = (const float4*)(x + ns * 40);
    float4 a = xr4[0], b = xr4[1], c = xr4[2], dd = xr4[3];
    xs[0]=a.x; xs[1]=a.y; xs[2]=a.z; xs[3]=a.w;
    xs[4]=b.x; xs[5]=b.y; xs[6]=b.z; xs[7]=b.w;
    xs[8]=c.x; xs[9]=c.y; xs[10]=c.z; xs[11]=c.w;
    xs[12]=dd.x; xs[13]=dd.y; xs[14]=dd.z; xs[15]=dd.w;
    float4 e = xr4[4], f = xr4[5], g2 = xr4[6], h = xr4[7], i2 = xr4[8], j = xr4[9];
    xv[0]=e.x; xv[1]=e.y; xv[2]=e.z; xv[3]=e.w;
    xv[4]=f.x; xv[5]=f.y; xv[6]=f.z; xv[7]=f.w;
    xv[8]=g2.x; xv[9]=g2.y; xv[10]=g2.z; xv[11]=g2.w;
    xv[12]=h.x; xv[13]=h.y; xv[14]=h.z; xv[15]=h.w;
    xv[16]=i2.x; xv[17]=i2.y; xv[18]=i2.z; xv[19]=i2.w;
    xv[20]=j.x; xv[21]=j.y; xv[22]=j.z; xv[23]=j.w;
}

__global__ void __launch_bounds__(128, 3)
gemm_kv_kernel(const float* __restrict__ x,
               const float* __restrict__ Wk2, const float* __restrict__ Wv2,
               const int* __restrict__ esrc, const int* __restrict__ edst,
               float* __restrict__ out)
{
    extern __shared__ char smem[];
    unsigned* sA32 = (unsigned*)smem;
    unsigned* sB32 = ((unsigned*)smem) + SA_U32;
    unsigned short* sB16 = (unsigned short*)sB32;
    float* sD = ((float*)smem) + SMD_F;
    const int tid = threadIdx.x;
    const int e = blockIdx.x * 128 + tid;
    const int lane = tid & 31;
    const int g = lane >> 2, cc = lane & 3;
    const int wbase = (tid >> 5) * 32;
    unsigned afr[2][2][4];

    // ---- shared prolog: features, geometry ----
    const int ns = esrc[e];
    const int nd = edst[e];
    float xs[16], xv[24];
    load_features(x, ns, xs, xv);
    float4 geo = g_geo[e];
    const float y10 = geo.x, y11 = geo.y, y12 = geo.z;
    float uv[8];
    #pragma unroll
    for (int i = 0; i < 8; i++)
        uv[i] = (xv[i*3+0]*y10 + xv[i*3+1]*y11 + xv[i*3+2]*y12) * INV_SQ3;

    // ================= Phase K =================
    STAGE_A(g_hk)
    STAGE_B(Wk2, 288, 0)
    __syncthreads();
    LOAD_AFR()

    float ks[8] = {0,0,0,0,0,0,0,0};
    float kv0[4] = {0,0,0,0}, kv1[4] = {0,0,0,0}, kv2[4] = {0,0,0,0};

    #pragma unroll
    for (int chunk = 0; chunk < 4; chunk++) {
        GEMM_CHUNK(chunk)
        #pragma unroll
        for (int jl2 = 0; jl2 < 36; jl2++) {
            float2 w2 = *(const float2*)&sD[tid * DPITCH + jl2 * 2];
            #pragma unroll
            for (int h2 = 0; h2 < 2; h2++) {
                const int j = chunk * 72 + jl2 * 2 + h2;
                float w = (h2 == 0) ? w2.x : w2.y;
                if (j < 128) {
                    ks[j & 7] = fmaf(xs[j >> 3], w, ks[j & 7]);
                } else if (j < 192) {
                    ks[j & 7] = fmaf(uv[(j - 128) >> 3], w, ks[j & 7]);
                } else if (j < 256) {
                    const int o = (j - 192) & 3;
                    float t = xs[(j - 192) >> 2] * w;
                    kv0[o] = fmaf(t, y10, kv0[o]);
                    kv1[o] = fmaf(t, y11, kv1[o]);
                    kv2[o] = fmaf(t, y12, kv2[o]);
                } else {
                    const int o = (j - 256) & 3, i = (j - 256) >> 2;
                    kv0[o] = fmaf(xv[i*3+0], w, kv0[o]);
                    kv1[o] = fmaf(xv[i*3+1], w, kv1[o]);
                    kv2[o] = fmaf(xv[i*3+2], w, kv2[o]);
                }
            }
        }
        __syncwarp();
    }

    float attn;
    {
        const float* qsw = g_qsw + nd * 8;
        const float* qvw = g_qvw + nd * 12;
        float sim = 0.f;
        #pragma unroll
        for (int o = 0; o < 8; o++) sim = fmaf(qsw[o], ks[o], sim);
        #pragma unroll
        for (int o = 0; o < 4; o++) {
            sim = fmaf(qvw[o*3+0], kv0[o], sim);
            sim = fmaf(qvw[o*3+1], kv1[o], sim);
            sim = fmaf(qvw[o*3+2], kv2[o], sim);
        }
        attn = expf(sim);
        atomicAdd(&g_Z[nd], attn);
    }

    // ================= Phase V =================
    float vs[16];
    float vv0[8], vv1[8], vv2[8];
    #pragma unroll
    for (int o = 0; o < 16; o++) vs[o] = 0.f;
    #pragma unroll
    for (int o = 0; o < 8; o++) { vv0[o] = 0.f; vv1[o] = 0.f; vv2[o] = 0.f; }

    __syncthreads();             // everyone done with K's sA/sB
    STAGE_A(g_hv)

    #pragma unroll
    for (int half = 0; half < 2; half++) {
        if (half == 1) __syncthreads();   // done with B half 0
        STAGE_B(Wv2, 576, half * 288)
        __syncthreads();
        if (half == 0) { LOAD_AFR() }

        #pragma unroll
        for (int chunk = 0; chunk < 4; chunk++) {
            GEMM_CHUNK(chunk)
            #pragma unroll
            for (int jl2 = 0; jl2 < 36; jl2++) {
                float2 w2 = *(const float2*)&sD[tid * DPITCH + jl2 * 2];
                #pragma unroll
                for (int h2 = 0; h2 < 2; h2++) {
                    const int j = half * 288 + chunk * 72 + jl2 * 2 + h2;
                    float w = (h2 == 0) ? w2.x : w2.y;
                    if (j < 256) {
                        vs[j & 15] = fmaf(xs[j >> 4], w, vs[j & 15]);
                    } else if (j < 384) {
                        vs[j & 15] = fmaf(uv[(j - 256) >> 4], w, vs[j & 15]);
                    } else if (j < 512) {
                        const int o = (j - 384) & 7;
                        float t = xs[(j - 384) >> 3] * w;
                        vv0[o] = fmaf(t, y10, vv0[o]);
                        vv1[o] = fmaf(t, y11, vv1[o]);
                        vv2[o] = fmaf(t, y12, vv2[o]);
                    } else {
                        const int o = (j - 512) & 7, i = (j - 512) >> 3;
                        vv0[o] = fmaf(xv[i*3+0], w, vv0[o]);
                        vv1[o] = fmaf(xv[i*3+1], w, vv1[o]);
                        vv2[o] = fmaf(xv[i*3+2], w, vv2[o]);
                    }
                }
            }
            __syncwarp();
        }
    }

    // scatter RAW attn * v (normalization by Z deferred)
    if (geo.w != 0.f) {
        float* orow = out + nd * 40;
        #pragma unroll
        for (int o = 0; o < 16; o++) atomicAdd(&orow[o], attn * vs[o]);
        #pragma unroll
        for (int o = 0; o < 8; o++) {
            atomicAdd(&orow[16 + o*3 + 0], attn * vv0[o]);
            atomicAdd(&orow[16 + o*3 + 1], attn * vv1[o]);
            atomicAdd(&orow[16 + o*3 + 2], attn * vv2[o]);
        }
    }
}

// =====================================================================
// Final: out[n][j] /= Z[n]
// =====================================================================
__global__ void normalize_out_kernel(float* __restrict__ out)
{
    int idx = blockIdx.x * blockDim.x + threadIdx.x;
    if (idx >= N_NODES * 40) return;
    out[idx] = out[idx] / g_Z[idx / 40];
}

// =====================================================================
extern "C" void kernel_launch(void* const* d_in, const int* in_sizes, int n_in,
                              void* d_out, int out_size)
{
    const float* pos   = (const float*)d_in[0];
    const float* x     = (const float*)d_in[1];
    const float* Wq_s  = (const float*)d_in[2];
    const float* Wq_v  = (const float*)d_in[3];
    const float* Wk1   = (const float*)d_in[4];
    const float* Wk2   = (const float*)d_in[5];
    const float* Wv1   = (const float*)d_in[6];
    const float* Wv2   = (const float*)d_in[7];
    const float* Ws_ss = (const float*)d_in[8];
    const float* Ws_vv = (const float*)d_in[9];
    const int*   esrc  = (const int*)d_in[10];
    const int*   edst  = (const int*)d_in[11];
    float* out = (float*)d_out;
    (void)in_sizes; (void)n_in; (void)out_size;

    cudaFuncSetAttribute(gemm_kv_kernel, cudaFuncAttributeMaxDynamicSharedMemorySize, SM_TOT);

    void* zptr = nullptr;
    cudaGetSymbolAddress(&zptr, g_Z);
    cudaMemsetAsync(zptr, 0, N_NODES * sizeof(float), 0);
    cudaMemsetAsync(out, 0, N_NODES * 40 * sizeof(float), 0);

    node_prep_kernel<<<(N_NODES + 255) / 256, 256>>>(x, Wq_s, Wq_v, Ws_ss, Ws_vv);
    basis_kernel<<<N_EDGES / 256, 256>>>(pos, Wk1, Wv1, esrc, edst);
    gemm_kv_kernel<<<N_EDGES / 128, 128, SM_TOT>>>(x, Wk2, Wv2, esrc, edst, out);
    normalize_out_kernel<<<(N_NODES * 40 + 255) / 256, 256>>>(out);
}